// round 15
// baseline (speedup 1.0000x reference)
#include <cuda_runtime.h>
#include <cuda_fp16.h>
#include <cstdint>
#include <math.h>

#define BB 8
#define SS 4096
#define DD 128
#define AA 128

#define QK_SCALE_L2E 0.12751744f   // (1/sqrt(128)) * log2(e)

// ---------------- scratch (static device globals; no allocations) ----------
__device__ float fa_pe[SS * DD];                 // 2 MB
__device__ __half fa_qh[BB * SS * AA];           // 8 MB each
__device__ __half fa_kh[BB * SS * AA];
__device__ __half fa_vh[BB * SS * AA];
__device__ __half fa_wh[3 * DD * AA];            // W hi/lo, pre-split
__device__ __half fa_wl[3 * DD * AA];

// ---------------- PTX helpers ----------------------------------------------
__device__ __forceinline__ unsigned int fa_smem_addr(const void* ptr) {
    unsigned int out;
    asm("{ .reg .u64 t; cvta.to.shared.u64 t, %1; cvt.u32.u64 %0, t; }"
        : "=r"(out) : "l"(ptr));
    return out;
}
__device__ __forceinline__ void fa_cp16(unsigned int dst, const void* src) {
    asm volatile("cp.async.cg.shared.global [%0], [%1], 16;" :: "r"(dst), "l"(src));
}
__device__ __forceinline__ void fa_cp_commit() {
    asm volatile("cp.async.commit_group;");
}
__device__ __forceinline__ void fa_cp_wait0() {
    asm volatile("cp.async.wait_group 0;");
}
__device__ __forceinline__ void fa_cp_waitg1() {
    asm volatile("cp.async.wait_group 1;");
}
__device__ __forceinline__ void fa_ldsm4(unsigned int* reg, unsigned int addr) {
    asm volatile("ldmatrix.sync.aligned.m8n8.x4.shared.b16 {%0,%1,%2,%3}, [%4];"
                 : "=r"(reg[0]), "=r"(reg[1]), "=r"(reg[2]), "=r"(reg[3]) : "r"(addr));
}
__device__ __forceinline__ void fa_ldsm4t(unsigned int* reg, unsigned int addr) {
    asm volatile("ldmatrix.sync.aligned.m8n8.x4.trans.shared.b16 {%0,%1,%2,%3}, [%4];"
                 : "=r"(reg[0]), "=r"(reg[1]), "=r"(reg[2]), "=r"(reg[3]) : "r"(addr));
}
__device__ __forceinline__ void fa_mma(float* acc, const unsigned int* afrag,
                                       const unsigned int* bfrag) {
    asm volatile("mma.sync.aligned.m16n8k16.row.col.f32.f16.f16.f32 "
                 "{%0,%1,%2,%3}, {%4,%5,%6,%7}, {%8,%9}, {%0,%1,%2,%3};"
                 : "+f"(acc[0]), "+f"(acc[1]), "+f"(acc[2]), "+f"(acc[3])
                 : "r"(afrag[0]), "r"(afrag[1]), "r"(afrag[2]), "r"(afrag[3]),
                   "r"(bfrag[0]), "r"(bfrag[1]));
}
__device__ __forceinline__ float fa_ex2(float x) {
    float r; asm("ex2.approx.f32 %0, %1;" : "=f"(r) : "f"(x)); return r;
}

// XOR-swizzled smem address: rows of 256B (128 fp16), 16B chunks permuted by row&7
__device__ __forceinline__ unsigned int fa_swz(unsigned int base, int row, int chunk) {
    return base + (unsigned int)row * 256u
                + (unsigned int)((chunk ^ (row & 7)) << 4);
}

// ---------------- kernel 0: positional encoding table ----------------------
__global__ void fa_pe_kernel() {
    int idx = blockIdx.x * blockDim.x + threadIdx.x;
    if (idx >= SS * (DD / 2)) return;
    int srow = idx / (DD / 2);
    int ii = idx % (DD / 2);
    float divv = expf((2.0f * (float)ii) * (-logf(10000.0f) / (float)DD));
    float ang = (float)srow * divv;
    fa_pe[srow * DD + 2 * ii]     = sinf(ang);
    fa_pe[srow * DD + 2 * ii + 1] = cosf(ang);
}

// ---------------- kernel 0b: split W matrices into fp16 hi/lo --------------
__global__ void fa_wsplit_kernel(const float* __restrict__ Wq,
                                 const float* __restrict__ Wk,
                                 const float* __restrict__ Wv) {
    int idx = blockIdx.x * blockDim.x + threadIdx.x;
    if (idx >= 3 * DD * AA) return;
    int wsel = idx / (DD * AA);
    int off = idx % (DD * AA);
    const float* Wm = (wsel == 0) ? Wq : (wsel == 1) ? Wk : Wv;
    float v = Wm[off];
    __half h = __float2half(v);
    fa_wh[idx] = h;
    fa_wl[idx] = __float2half(v - __half2float(h));
}

// ---------------- kernel 1: tensor-core projection (fp16x2) ----------------
#define PR_X  0
#define PR_WH 32768
#define PR_WL 65536
#define PR_SMEM 98304

__global__ __launch_bounds__(256, 1) void pr_proj_kernel(
    const float* __restrict__ xin,
    const float* __restrict__ bq,
    const float* __restrict__ bk,
    const float* __restrict__ bv)
{
    extern __shared__ char pr_sm[];
    unsigned int sb = fa_smem_addr(pr_sm);

    int wsel = blockIdx.y;
    const float* bias = (wsel == 0) ? bq : (wsel == 1) ? bk : bv;
    __half* dst = (wsel == 0) ? fa_qh : (wsel == 1) ? fa_kh : fa_vh;
    float scl = (wsel == 0) ? QK_SCALE_L2E : 1.0f;

    int tid = threadIdx.x;
    int warp = tid >> 5, lane = tid & 31;
    int rowBase = blockIdx.x * 128;

    const __half* Wh = fa_wh + wsel * DD * AA;
    const __half* Wl = fa_wl + wsel * DD * AA;
#pragma unroll
    for (int i = 0; i < 8; i++) {
        int cid = tid + 256 * i;              // 128 rows x 16 chunks
        int row = cid >> 4, chk = cid & 15;
        unsigned int dsw = (unsigned int)row * 256u
                         + (unsigned int)((chk ^ (row & 7)) << 4);
        fa_cp16(sb + PR_WH + dsw, Wh + (long long)row * AA + chk * 8);
        fa_cp16(sb + PR_WL + dsw, Wl + (long long)row * AA + chk * 8);
    }
    fa_cp_commit();

#pragma unroll
    for (int i = 0; i < 8; i++) {
        int cid = tid + 256 * i;
        int row = cid >> 4, chk = cid & 15;
        unsigned int dsw = (unsigned int)row * 256u
                         + (unsigned int)((chk ^ (row & 7)) << 4);
        int grow = rowBase + row;
        int srow = grow & (SS - 1);
        const float4* xp = reinterpret_cast<const float4*>(
            xin + (long long)grow * DD + chk * 8);
        const float4* pp = reinterpret_cast<const float4*>(
            fa_pe + srow * DD + chk * 8);
        float4 a0 = xp[0], a1 = xp[1];
        float4 p0 = pp[0], p1 = pp[1];
        __half2 h0 = __floats2half2_rn(a0.x + p0.x, a0.y + p0.y);
        __half2 h1 = __floats2half2_rn(a0.z + p0.z, a0.w + p0.w);
        __half2 h2 = __floats2half2_rn(a1.x + p1.x, a1.y + p1.y);
        __half2 h3 = __floats2half2_rn(a1.z + p1.z, a1.w + p1.w);
        asm volatile("st.shared.v4.b32 [%0], {%1,%2,%3,%4};"
                     :: "r"(sb + PR_X + dsw),
                        "r"(*reinterpret_cast<unsigned int*>(&h0)),
                        "r"(*reinterpret_cast<unsigned int*>(&h1)),
                        "r"(*reinterpret_cast<unsigned int*>(&h2)),
                        "r"(*reinterpret_cast<unsigned int*>(&h3)));
    }
    fa_cp_wait0();
    __syncthreads();

    float acc[16][4];
#pragma unroll
    for (int nc = 0; nc < 16; nc++)
#pragma unroll
        for (int j = 0; j < 4; j++) acc[nc][j] = 0.0f;

    int aRow = warp * 16 + (lane & 15);
    int aSel = lane >> 4;
    int vRow = lane & 15;
    int vSel = lane >> 4;

#pragma unroll
    for (int kk = 0; kk < 8; kk++) {
        unsigned int afh[4];
        fa_ldsm4(afh, fa_swz(sb + PR_X, aRow, 2 * kk + aSel));
#pragma unroll
        for (int np = 0; np < 8; np++) {
            unsigned int bh4[4], bl4[4];
            fa_ldsm4t(bh4, fa_swz(sb + PR_WH, kk * 16 + vRow, 2 * np + vSel));
            fa_ldsm4t(bl4, fa_swz(sb + PR_WL, kk * 16 + vRow, 2 * np + vSel));
            fa_mma(acc[2 * np], afh, bh4);
            fa_mma(acc[2 * np], afh, bl4);
            fa_mma(acc[2 * np + 1], afh, bh4 + 2);
            fa_mma(acc[2 * np + 1], afh, bl4 + 2);
        }
    }

    int rowA = rowBase + warp * 16 + (lane >> 2);
    int colB = (lane & 3) * 2;
#pragma unroll
    for (int nc = 0; nc < 16; nc++) {
        int cc = nc * 8 + colB;
        float b0 = bias[cc], b1 = bias[cc + 1];
        float v00 = (acc[nc][0] + b0) * scl, v01 = (acc[nc][1] + b1) * scl;
        float v10 = (acc[nc][2] + b0) * scl, v11 = (acc[nc][3] + b1) * scl;
        *reinterpret_cast<__half2*>(dst + (long long)rowA * AA + cc) =
            __floats2half2_rn(v00, v01);
        *reinterpret_cast<__half2*>(dst + (long long)(rowA + 8) * AA + cc) =
            __floats2half2_rn(v10, v11);
    }
}

// ---------------- kernel 2: flash attention, fp16 tensor-core --------------
// BR=64 (4 warps x 16 rows), 128 threads, 2 CTAs/SM for latency hiding.
// 2-stage KV ring, two syncs per tile (prefetch strictly after all reads).
#define FA_BR 64
#define FA_BC 64
#define FA_NT (SS / FA_BC)

#define FA_QH_OFF 0
#define FA_BUF_OFF 16384
#define FA_BUF_SZ 32768           // per stage: Kh, Vh @ 16KB each
#define FA_KH_OFF 0
#define FA_VH_OFF 16384
#define FA_ATTN_SMEM (FA_BUF_OFF + 2 * FA_BUF_SZ)   // 80 KB -> 2 CTAs/SM

__device__ __forceinline__ void fa_prefetch_kv(unsigned int sbase, int buf,
                                               int tile0, int bidx, int tid) {
    const __half* Kh = fa_kh + (long long)bidx * SS * AA;
    const __half* Vh = fa_vh + (long long)bidx * SS * AA;
    unsigned int base = sbase + FA_BUF_OFF + (unsigned int)buf * FA_BUF_SZ;
#pragma unroll
    for (int i = 0; i < 8; i++) {
        int cid = tid + 128 * i;            // 64 rows x 16 chunks
        int row = cid >> 4;
        int chk = cid & 15;
        unsigned int dsw = (unsigned int)row * 256u
                         + (unsigned int)((chk ^ (row & 7)) << 4);
        long long gof = (long long)(tile0 + row) * AA + chk * 8;
        fa_cp16(base + FA_KH_OFF + dsw, Kh + gof);
        fa_cp16(base + FA_VH_OFF + dsw, Vh + gof);
    }
}

__global__ __launch_bounds__(128, 2) void fa_attn_kernel(float* __restrict__ attnOut) {
    extern __shared__ char fa_smem_raw[];
    unsigned int sbase = fa_smem_addr(fa_smem_raw);

    int bidx = blockIdx.y;
    int qbase = blockIdx.x * FA_BR;
    int tid = threadIdx.x;
    int warp = tid >> 5;
    int lane = tid & 31;
    int rwarp = warp * 16;

    const __half* Qh = fa_qh + (long long)bidx * SS * AA;

    // group 0: Q (64 rows) + KV tile 0
#pragma unroll
    for (int i = 0; i < 8; i++) {
        int cid = tid + 128 * i;              // 64 rows x 16 chunks
        int row = cid >> 4;
        int chk = cid & 15;
        unsigned int dsw = (unsigned int)row * 256u
                         + (unsigned int)((chk ^ (row & 7)) << 4);
        fa_cp16(sbase + FA_QH_OFF + dsw,
                Qh + (long long)(qbase + row) * AA + chk * 8);
    }
    fa_prefetch_kv(sbase, 0, 0, bidx, tid);
    fa_cp_commit();
    // group 1: KV tile 1
    fa_prefetch_kv(sbase, 1, FA_BC, bidx, tid);
    fa_cp_commit();

    float rdenA = 0.0f, rdenB = 0.0f;
    float oacc[16][4];
#pragma unroll
    for (int i = 0; i < 16; i++)
#pragma unroll
        for (int j = 0; j < 4; j++) oacc[i][j] = 0.0f;

    // per-lane ldmatrix indices
    int aRow  = rwarp + (lane & 15);          // Q A-frags
    int aSel  = lane >> 4;
    int kMat  = lane >> 3;                    // K paired x4: mat id 0..3
    int kRow  = ((kMat >> 1) << 3) + (lane & 7);
    int kSel  = kMat & 1;
    int vRow  = lane & 15;                    // V paired x4-trans
    int vSel  = lane >> 4;

    unsigned int qreg[8][4];                  // Q fragments, loaded once at t=0

    for (int t = 0; t < FA_NT; t++) {
        fa_cp_waitg1();         // group t complete: K(t), V(t) resident
        __syncthreads();

        if (t == 0) {
#pragma unroll
            for (int kk = 0; kk < 8; kk++)
                fa_ldsm4(qreg[kk], fa_swz(sbase + FA_QH_OFF, aRow, 2 * kk + aSel));
        }

        unsigned int kvb = sbase + FA_BUF_OFF + (unsigned int)(t & 1) * FA_BUF_SZ;

        // ---- S' = Qs K^T (scale*log2e folded into Q), single fp16 ----
        float sfr[8][4];
#pragma unroll
        for (int nc = 0; nc < 8; nc++)
#pragma unroll
            for (int j = 0; j < 4; j++) sfr[nc][j] = 0.0f;

#pragma unroll
        for (int kk = 0; kk < 8; kk++) {
#pragma unroll
            for (int np = 0; np < 4; np++) {
                unsigned int bk4[4];
                fa_ldsm4(bk4, fa_swz(kvb + FA_KH_OFF, np * 16 + kRow, 2 * kk + kSel));
                fa_mma(sfr[2 * np], qreg[kk], bk4);
                fa_mma(sfr[2 * np + 1], qreg[kk], bk4 + 2);
            }
        }

        // ---- P = 2^(S'), accumulate row sums thread-locally ----
        float psumA = 0.0f, psumB = 0.0f;
#pragma unroll
        for (int nc = 0; nc < 8; nc++) {
            sfr[nc][0] = fa_ex2(sfr[nc][0]);
            sfr[nc][1] = fa_ex2(sfr[nc][1]);
            sfr[nc][2] = fa_ex2(sfr[nc][2]);
            sfr[nc][3] = fa_ex2(sfr[nc][3]);
            psumA += sfr[nc][0] + sfr[nc][1];
            psumB += sfr[nc][2] + sfr[nc][3];
        }
        rdenA += psumA;
        rdenB += psumB;

        // ---- build P fragments (single fp16) ----
        unsigned int pfh[4][4];
#pragma unroll
        for (int tt = 0; tt < 4; tt++) {
#pragma unroll
            for (int rr = 0; rr < 4; rr++) {
                int nc = 2 * tt + (rr >> 1);
                int j0 = (rr & 1) * 2;
                __half2 hpair = __floats2half2_rn(sfr[nc][j0], sfr[nc][j0 + 1]);
                int ai = (rr >> 1) * 2 + (rr & 1);
                pfh[tt][ai] = *reinterpret_cast<unsigned int*>(&hpair);
            }
        }

        // ---- O += P V, paired V x4-trans ----
#pragma unroll
        for (int op = 0; op < 8; op++) {
#pragma unroll
            for (int tt = 0; tt < 4; tt++) {
                unsigned int v4[4];
                fa_ldsm4t(v4, fa_swz(kvb + FA_VH_OFF, tt * 16 + vRow, 2 * op + vSel));
                fa_mma(oacc[2 * op], pfh[tt], v4);
                fa_mma(oacc[2 * op + 1], pfh[tt], v4 + 2);
            }
        }

        __syncthreads();        // all reads of slot t&1 complete
        if (t + 2 < FA_NT)
            fa_prefetch_kv(sbase, t & 1, (t + 2) * FA_BC, bidx, tid);
        fa_cp_commit();         // one commit per iter keeps group count exact
    }

    // ---- final row-sum reduce (quad) + normalize + write ----
    rdenA += __shfl_xor_sync(0xffffffffu, rdenA, 1);
    rdenA += __shfl_xor_sync(0xffffffffu, rdenA, 2);
    rdenB += __shfl_xor_sync(0xffffffffu, rdenB, 1);
    rdenB += __shfl_xor_sync(0xffffffffu, rdenB, 2);
    float invA = 1.0f / rdenA;
    float invB = 1.0f / rdenB;
    int rowA = qbase + rwarp + (lane >> 2);
    int colB = (lane & 3) * 2;
    float* outBase = attnOut + (long long)bidx * SS * AA;
#pragma unroll
    for (int oc = 0; oc < 16; oc++) {
        float2 vA = make_float2(oacc[oc][0] * invA, oacc[oc][1] * invA);
        float2 vB = make_float2(oacc[oc][2] * invB, oacc[oc][3] * invB);
        *reinterpret_cast<float2*>(outBase + (long long)rowA * AA + oc * 8 + colB) = vA;
        *reinterpret_cast<float2*>(outBase + (long long)(rowA + 8) * AA + oc * 8 + colB) = vB;
    }
}

// ---------------- launch ----------------------------------------------------
extern "C" void kernel_launch(void* const* d_in, const int* in_sizes, int n_in,
                              void* d_out, int out_size) {
    const float* xin = (const float*)d_in[0];
    const float* Wq  = (const float*)d_in[1];
    const float* bq  = (const float*)d_in[2];
    const float* Wk  = (const float*)d_in[3];
    const float* bk  = (const float*)d_in[4];
    const float* Wv  = (const float*)d_in[5];
    const float* bv  = (const float*)d_in[6];
    float* outp = (float*)d_out;

    cudaFuncSetAttribute(pr_proj_kernel,
                         cudaFuncAttributeMaxDynamicSharedMemorySize, PR_SMEM);
    cudaFuncSetAttribute(fa_attn_kernel,
                         cudaFuncAttributeMaxDynamicSharedMemorySize, FA_ATTN_SMEM);

    fa_pe_kernel<<<(SS * (DD / 2) + 255) / 256, 256>>>();
    fa_wsplit_kernel<<<(3 * DD * AA + 255) / 256, 256>>>(Wq, Wk, Wv);
    pr_proj_kernel<<<dim3(BB * SS / 128, 3), 256, PR_SMEM>>>(xin, bq, bk, bv);
    fa_attn_kernel<<<dim3(SS / FA_BR, BB), 128, FA_ATTN_SMEM>>>(outp);
}

// round 16
// speedup vs baseline: 1.6012x; 1.6012x over previous
#include <cuda_runtime.h>
#include <cuda_fp16.h>
#include <cstdint>
#include <math.h>

#define BB 8
#define SS 4096
#define DD 128
#define AA 128

#define QK_SCALE_L2E 0.12751744f   // (1/sqrt(128)) * log2(e)

// ---------------- scratch (static device globals; no allocations) ----------
__device__ float fa_pe[SS * DD];                 // 2 MB
__device__ __half fa_qh[BB * SS * AA];           // 8 MB each
__device__ __half fa_kh[BB * SS * AA];
__device__ __half fa_vh[BB * SS * AA];
__device__ __half fa_wh[3 * DD * AA];            // W hi/lo, pre-split
__device__ __half fa_wl[3 * DD * AA];

// ---------------- PTX helpers ----------------------------------------------
__device__ __forceinline__ unsigned int fa_smem_addr(const void* ptr) {
    unsigned int out;
    asm("{ .reg .u64 t; cvta.to.shared.u64 t, %1; cvt.u32.u64 %0, t; }"
        : "=r"(out) : "l"(ptr));
    return out;
}
__device__ __forceinline__ void fa_cp16(unsigned int dst, const void* src) {
    asm volatile("cp.async.cg.shared.global [%0], [%1], 16;" :: "r"(dst), "l"(src));
}
__device__ __forceinline__ void fa_cp_commit() {
    asm volatile("cp.async.commit_group;");
}
__device__ __forceinline__ void fa_cp_wait0() {
    asm volatile("cp.async.wait_group 0;");
}
__device__ __forceinline__ void fa_cp_wait2() {
    asm volatile("cp.async.wait_group 2;");
}
__device__ __forceinline__ void fa_ldsm4(unsigned int* reg, unsigned int addr) {
    asm volatile("ldmatrix.sync.aligned.m8n8.x4.shared.b16 {%0,%1,%2,%3}, [%4];"
                 : "=r"(reg[0]), "=r"(reg[1]), "=r"(reg[2]), "=r"(reg[3]) : "r"(addr));
}
__device__ __forceinline__ void fa_ldsm4t(unsigned int* reg, unsigned int addr) {
    asm volatile("ldmatrix.sync.aligned.m8n8.x4.trans.shared.b16 {%0,%1,%2,%3}, [%4];"
                 : "=r"(reg[0]), "=r"(reg[1]), "=r"(reg[2]), "=r"(reg[3]) : "r"(addr));
}
__device__ __forceinline__ void fa_mma(float* acc, const unsigned int* afrag,
                                       const unsigned int* bfrag) {
    asm volatile("mma.sync.aligned.m16n8k16.row.col.f32.f16.f16.f32 "
                 "{%0,%1,%2,%3}, {%4,%5,%6,%7}, {%8,%9}, {%0,%1,%2,%3};"
                 : "+f"(acc[0]), "+f"(acc[1]), "+f"(acc[2]), "+f"(acc[3])
                 : "r"(afrag[0]), "r"(afrag[1]), "r"(afrag[2]), "r"(afrag[3]),
                   "r"(bfrag[0]), "r"(bfrag[1]));
}
__device__ __forceinline__ float fa_ex2(float x) {
    float r; asm("ex2.approx.f32 %0, %1;" : "=f"(r) : "f"(x)); return r;
}

// XOR-swizzled smem address: rows of 256B (128 fp16), 16B chunks permuted by row&7
__device__ __forceinline__ unsigned int fa_swz(unsigned int base, int row, int chunk) {
    return base + (unsigned int)row * 256u
                + (unsigned int)((chunk ^ (row & 7)) << 4);
}

// ---------------- kernel 0: positional encoding table ----------------------
__global__ void fa_pe_kernel() {
    int idx = blockIdx.x * blockDim.x + threadIdx.x;
    if (idx >= SS * (DD / 2)) return;
    int srow = idx / (DD / 2);
    int ii = idx % (DD / 2);
    float divv = expf((2.0f * (float)ii) * (-logf(10000.0f) / (float)DD));
    float ang = (float)srow * divv;
    fa_pe[srow * DD + 2 * ii]     = sinf(ang);
    fa_pe[srow * DD + 2 * ii + 1] = cosf(ang);
}

// ---------------- kernel 0b: split W matrices into fp16 hi/lo --------------
__global__ void fa_wsplit_kernel(const float* __restrict__ Wq,
                                 const float* __restrict__ Wk,
                                 const float* __restrict__ Wv) {
    int idx = blockIdx.x * blockDim.x + threadIdx.x;
    if (idx >= 3 * DD * AA) return;
    int wsel = idx / (DD * AA);
    int off = idx % (DD * AA);
    const float* Wm = (wsel == 0) ? Wq : (wsel == 1) ? Wk : Wv;
    float v = Wm[off];
    __half h = __float2half(v);
    fa_wh[idx] = h;
    fa_wl[idx] = __float2half(v - __half2float(h));
}

// ---------------- kernel 1: tensor-core projection (fp16x2) ----------------
#define PR_X  0
#define PR_WH 32768
#define PR_WL 65536
#define PR_SMEM 98304

__global__ __launch_bounds__(256, 1) void pr_proj_kernel(
    const float* __restrict__ xin,
    const float* __restrict__ bq,
    const float* __restrict__ bk,
    const float* __restrict__ bv)
{
    extern __shared__ char pr_sm[];
    unsigned int sb = fa_smem_addr(pr_sm);

    int wsel = blockIdx.y;
    const float* bias = (wsel == 0) ? bq : (wsel == 1) ? bk : bv;
    __half* dst = (wsel == 0) ? fa_qh : (wsel == 1) ? fa_kh : fa_vh;
    float scl = (wsel == 0) ? QK_SCALE_L2E : 1.0f;

    int tid = threadIdx.x;
    int warp = tid >> 5, lane = tid & 31;
    int rowBase = blockIdx.x * 128;

    const __half* Wh = fa_wh + wsel * DD * AA;
    const __half* Wl = fa_wl + wsel * DD * AA;
#pragma unroll
    for (int i = 0; i < 8; i++) {
        int cid = tid + 256 * i;              // 128 rows x 16 chunks
        int row = cid >> 4, chk = cid & 15;
        unsigned int dsw = (unsigned int)row * 256u
                         + (unsigned int)((chk ^ (row & 7)) << 4);
        fa_cp16(sb + PR_WH + dsw, Wh + (long long)row * AA + chk * 8);
        fa_cp16(sb + PR_WL + dsw, Wl + (long long)row * AA + chk * 8);
    }
    fa_cp_commit();

#pragma unroll
    for (int i = 0; i < 8; i++) {
        int cid = tid + 256 * i;
        int row = cid >> 4, chk = cid & 15;
        unsigned int dsw = (unsigned int)row * 256u
                         + (unsigned int)((chk ^ (row & 7)) << 4);
        int grow = rowBase + row;
        int srow = grow & (SS - 1);
        const float4* xp = reinterpret_cast<const float4*>(
            xin + (long long)grow * DD + chk * 8);
        const float4* pp = reinterpret_cast<const float4*>(
            fa_pe + srow * DD + chk * 8);
        float4 a0 = xp[0], a1 = xp[1];
        float4 p0 = pp[0], p1 = pp[1];
        __half2 h0 = __floats2half2_rn(a0.x + p0.x, a0.y + p0.y);
        __half2 h1 = __floats2half2_rn(a0.z + p0.z, a0.w + p0.w);
        __half2 h2 = __floats2half2_rn(a1.x + p1.x, a1.y + p1.y);
        __half2 h3 = __floats2half2_rn(a1.z + p1.z, a1.w + p1.w);
        asm volatile("st.shared.v4.b32 [%0], {%1,%2,%3,%4};"
                     :: "r"(sb + PR_X + dsw),
                        "r"(*reinterpret_cast<unsigned int*>(&h0)),
                        "r"(*reinterpret_cast<unsigned int*>(&h1)),
                        "r"(*reinterpret_cast<unsigned int*>(&h2)),
                        "r"(*reinterpret_cast<unsigned int*>(&h3)));
    }
    fa_cp_wait0();
    __syncthreads();

    float acc[16][4];
#pragma unroll
    for (int nc = 0; nc < 16; nc++)
#pragma unroll
        for (int j = 0; j < 4; j++) acc[nc][j] = 0.0f;

    int aRow = warp * 16 + (lane & 15);
    int aSel = lane >> 4;
    int vRow = lane & 15;
    int vSel = lane >> 4;

#pragma unroll
    for (int kk = 0; kk < 8; kk++) {
        unsigned int afh[4];
        fa_ldsm4(afh, fa_swz(sb + PR_X, aRow, 2 * kk + aSel));
#pragma unroll
        for (int np = 0; np < 8; np++) {
            unsigned int bh4[4], bl4[4];
            fa_ldsm4t(bh4, fa_swz(sb + PR_WH, kk * 16 + vRow, 2 * np + vSel));
            fa_ldsm4t(bl4, fa_swz(sb + PR_WL, kk * 16 + vRow, 2 * np + vSel));
            fa_mma(acc[2 * np], afh, bh4);
            fa_mma(acc[2 * np], afh, bl4);
            fa_mma(acc[2 * np + 1], afh, bh4 + 2);
            fa_mma(acc[2 * np + 1], afh, bl4 + 2);
        }
    }

    int rowA = rowBase + warp * 16 + (lane >> 2);
    int colB = (lane & 3) * 2;
#pragma unroll
    for (int nc = 0; nc < 16; nc++) {
        int cc = nc * 8 + colB;
        float b0 = bias[cc], b1 = bias[cc + 1];
        float v00 = (acc[nc][0] + b0) * scl, v01 = (acc[nc][1] + b1) * scl;
        float v10 = (acc[nc][2] + b0) * scl, v11 = (acc[nc][3] + b1) * scl;
        *reinterpret_cast<__half2*>(dst + (long long)rowA * AA + cc) =
            __floats2half2_rn(v00, v01);
        *reinterpret_cast<__half2*>(dst + (long long)(rowA + 8) * AA + cc) =
            __floats2half2_rn(v10, v11);
    }
}

// ---------------- kernel 2: flash attention, fp16 tensor-core --------------
// R13 base (BR=128, 8 warps, 4-stage ring, one sync/tile, Q in registers)
// + quarter-tile interleave: per tt, QK(16 mma) -> exp/pack -> PV(16 mma),
//   so exp(tt) overlaps the PV(tt-1) drain on the tensor pipe.
#define FA_BR 128
#define FA_BC 64
#define FA_NT (SS / FA_BC)

#define FA_QH_OFF 0
#define FA_BUF_OFF 32768
#define FA_BUF_SZ 32768           // per stage: Kh, Vh @ 16KB each
#define FA_KH_OFF 0
#define FA_VH_OFF 16384
#define FA_ATTN_SMEM (FA_BUF_OFF + 4 * FA_BUF_SZ)   // 160 KB

__device__ __forceinline__ void fa_prefetch_kv(unsigned int sbase, int buf,
                                               int tile0, int bidx, int tid) {
    const __half* Kh = fa_kh + (long long)bidx * SS * AA;
    const __half* Vh = fa_vh + (long long)bidx * SS * AA;
    unsigned int base = sbase + FA_BUF_OFF + (unsigned int)buf * FA_BUF_SZ;
#pragma unroll
    for (int i = 0; i < 4; i++) {
        int cid = tid + 256 * i;            // 64 rows x 16 chunks
        int row = cid >> 4;
        int chk = cid & 15;
        unsigned int dsw = (unsigned int)row * 256u
                         + (unsigned int)((chk ^ (row & 7)) << 4);
        long long gof = (long long)(tile0 + row) * AA + chk * 8;
        fa_cp16(base + FA_KH_OFF + dsw, Kh + gof);
        fa_cp16(base + FA_VH_OFF + dsw, Vh + gof);
    }
}

__global__ __launch_bounds__(256, 1) void fa_attn_kernel(float* __restrict__ attnOut) {
    extern __shared__ char fa_smem_raw[];
    unsigned int sbase = fa_smem_addr(fa_smem_raw);

    int bidx = blockIdx.y;
    int qbase = blockIdx.x * FA_BR;
    int tid = threadIdx.x;
    int warp = tid >> 5;
    int lane = tid & 31;
    int rwarp = warp * 16;

    const __half* Qh = fa_qh + (long long)bidx * SS * AA;

    // group 0: Q + KV tile 0
#pragma unroll
    for (int i = 0; i < 8; i++) {
        int cid = tid + 256 * i;              // 128 rows x 16 chunks
        int row = cid >> 4;
        int chk = cid & 15;
        unsigned int dsw = (unsigned int)row * 256u
                         + (unsigned int)((chk ^ (row & 7)) << 4);
        fa_cp16(sbase + FA_QH_OFF + dsw,
                Qh + (long long)(qbase + row) * AA + chk * 8);
    }
    fa_prefetch_kv(sbase, 0, 0, bidx, tid);
    fa_cp_commit();
    // group 1: KV tile 1
    fa_prefetch_kv(sbase, 1, FA_BC, bidx, tid);
    fa_cp_commit();

    float rdenA = 0.0f, rdenB = 0.0f;
    float oacc[16][4];
#pragma unroll
    for (int i = 0; i < 16; i++)
#pragma unroll
        for (int j = 0; j < 4; j++) oacc[i][j] = 0.0f;

    // per-lane ldmatrix indices
    int aRow  = rwarp + (lane & 15);          // Q A-frags
    int aSel  = lane >> 4;
    int kMat  = lane >> 3;                    // K paired x4: mat id 0..3
    int kRow  = ((kMat >> 1) << 3) + (lane & 7);
    int kSel  = kMat & 1;
    int vRow  = lane & 15;                    // V paired x4-trans
    int vSel  = lane >> 4;

    unsigned int qreg[8][4];                  // Q fragments, loaded once at t=0

    for (int t = 0; t < FA_NT; t++) {
        if (t + 2 < FA_NT)
            fa_prefetch_kv(sbase, (t + 2) & 3, (t + 2) * FA_BC, bidx, tid);
        fa_cp_commit();
        fa_cp_wait2();          // own group t complete
        __syncthreads();        // all threads' group-t copies visible

        if (t == 0) {
#pragma unroll
            for (int kk = 0; kk < 8; kk++)
                fa_ldsm4(qreg[kk], fa_swz(sbase + FA_QH_OFF, aRow, 2 * kk + aSel));
        }

        unsigned int kvb = sbase + FA_BUF_OFF + (unsigned int)(t & 3) * FA_BUF_SZ;

        // ---- quarter-tile streams: per tt (16 S-cols): QK -> exp -> PV ----
#pragma unroll
        for (int tt = 0; tt < 4; tt++) {
            // S' cols tt*16..tt*16+15 = Qs K^T (K rows tt*16..tt*16+15)
            float s0[4], s1[4];
#pragma unroll
            for (int j = 0; j < 4; j++) { s0[j] = 0.0f; s1[j] = 0.0f; }
#pragma unroll
            for (int kk = 0; kk < 8; kk++) {
                unsigned int bk4[4];
                fa_ldsm4(bk4, fa_swz(kvb + FA_KH_OFF, tt * 16 + kRow, 2 * kk + kSel));
                fa_mma(s0, qreg[kk], bk4);
                fa_mma(s1, qreg[kk], bk4 + 2);
            }

            // exp + row sums + pack P fragment tt
            float e00 = fa_ex2(s0[0]), e01 = fa_ex2(s0[1]);
            float e02 = fa_ex2(s0[2]), e03 = fa_ex2(s0[3]);
            float e10 = fa_ex2(s1[0]), e11 = fa_ex2(s1[1]);
            float e12 = fa_ex2(s1[2]), e13 = fa_ex2(s1[3]);
            rdenA += e00 + e01 + e10 + e11;
            rdenB += e02 + e03 + e12 + e13;

            unsigned int pfh[4];
            {
                __half2 a0 = __floats2half2_rn(e00, e01);   // (rowA, nc-lo)
                __half2 a1 = __floats2half2_rn(e02, e03);   // (rowB, nc-lo)
                __half2 a2 = __floats2half2_rn(e10, e11);   // (rowA, nc-hi)
                __half2 a3 = __floats2half2_rn(e12, e13);   // (rowB, nc-hi)
                pfh[0] = *reinterpret_cast<unsigned int*>(&a0);
                pfh[1] = *reinterpret_cast<unsigned int*>(&a1);
                pfh[2] = *reinterpret_cast<unsigned int*>(&a2);
                pfh[3] = *reinterpret_cast<unsigned int*>(&a3);
            }

            // O += P(:, tt-chunk) V(tt-chunk, :)
#pragma unroll
            for (int op = 0; op < 8; op++) {
                unsigned int v4[4];
                fa_ldsm4t(v4, fa_swz(kvb + FA_VH_OFF, tt * 16 + vRow, 2 * op + vSel));
                fa_mma(oacc[2 * op], pfh, v4);
                fa_mma(oacc[2 * op + 1], pfh, v4 + 2);
            }
        }
    }

    // ---- final row-sum reduce (quad) + normalize + write ----
    rdenA += __shfl_xor_sync(0xffffffffu, rdenA, 1);
    rdenA += __shfl_xor_sync(0xffffffffu, rdenA, 2);
    rdenB += __shfl_xor_sync(0xffffffffu, rdenB, 1);
    rdenB += __shfl_xor_sync(0xffffffffu, rdenB, 2);
    float invA = 1.0f / rdenA;
    float invB = 1.0f / rdenB;
    int rowA = qbase + rwarp + (lane >> 2);
    int colB = (lane & 3) * 2;
    float* outBase = attnOut + (long long)bidx * SS * AA;
#pragma unroll
    for (int oc = 0; oc < 16; oc++) {
        float2 vA = make_float2(oacc[oc][0] * invA, oacc[oc][1] * invA);
        float2 vB = make_float2(oacc[oc][2] * invB, oacc[oc][3] * invB);
        *reinterpret_cast<float2*>(outBase + (long long)rowA * AA + oc * 8 + colB) = vA;
        *reinterpret_cast<float2*>(outBase + (long long)(rowA + 8) * AA + oc * 8 + colB) = vB;
    }
}

// ---------------- launch ----------------------------------------------------
extern "C" void kernel_launch(void* const* d_in, const int* in_sizes, int n_in,
                              void* d_out, int out_size) {
    const float* xin = (const float*)d_in[0];
    const float* Wq  = (const float*)d_in[1];
    const float* bq  = (const float*)d_in[2];
    const float* Wk  = (const float*)d_in[3];
    const float* bk  = (const float*)d_in[4];
    const float* Wv  = (const float*)d_in[5];
    const float* bv  = (const float*)d_in[6];
    float* outp = (float*)d_out;

    cudaFuncSetAttribute(pr_proj_kernel,
                         cudaFuncAttributeMaxDynamicSharedMemorySize, PR_SMEM);
    cudaFuncSetAttribute(fa_attn_kernel,
                         cudaFuncAttributeMaxDynamicSharedMemorySize, FA_ATTN_SMEM);

    fa_pe_kernel<<<(SS * (DD / 2) + 255) / 256, 256>>>();
    fa_wsplit_kernel<<<(3 * DD * AA + 255) / 256, 256>>>(Wq, Wk, Wv);
    pr_proj_kernel<<<dim3(BB * SS / 128, 3), 256, PR_SMEM>>>(xin, bq, bk, bv);
    fa_attn_kernel<<<dim3(SS / FA_BR, BB), 256, FA_ATTN_SMEM>>>(outp);
}